// round 4
// baseline (speedup 1.0000x reference)
#include <cuda_runtime.h>
#include <cmath>

// Problem constants (fixed by the reference)
#define BATCH   2
#define LSEQ    2048
#define DMODEL  1024
#define DINNER  2048
#define DSTATE  16
#define NROWS   (BATCH*LSEQ)          // 4096 token rows
#define XZW     (2*DINNER)            // 4096 (x_ | z)

// ---------------- scratch (static device arrays; no allocation) ------------
__device__ float g_xz   [(size_t)NROWS * XZW];     // 64 MB : x@W_in
__device__ float g_xs   [(size_t)NROWS * DINNER];  // 32 MB : silu(conv(x_))
__device__ float g_dt   [(size_t)NROWS * DINNER];  // 32 MB : softplus(delta*w_dt+b_dt)
__device__ float g_yz   [(size_t)NROWS * DINNER];  // 32 MB : (y + x*Dp)*silu(z)
__device__ float g_Bc   [(size_t)NROWS * DSTATE];  // B_t
__device__ float g_Cc   [(size_t)NROWS * DSTATE];  // C_t
__device__ float g_delta[NROWS];                   // raw dt scalar per token

// ============================================================================
// SGEMM: C[M,N] = A[M,K] @ B[K,N], all row-major, M%128==0, N%128==0, K%16==0
// 128x128 block tile, 8x8 per thread, 256 threads, register prefetch.
// ============================================================================
__global__ __launch_bounds__(256) void sgemm_k(
    const float* __restrict__ A, const float* __restrict__ B,
    float* __restrict__ C, int M, int N, int K)
{
    __shared__ float As[16][132];   // [k][m], padded to kill STS conflicts
    __shared__ float Bs[16][128];   // [k][n]

    const int tid = threadIdx.x;
    const int bm  = blockIdx.y * 128;
    const int bn  = blockIdx.x * 128;

    const int aRow  = tid >> 2;          // 0..63
    const int aCol4 = tid & 3;           // k-offset = aCol4*4
    const int bRow  = tid >> 5;          // 0..7
    const int bCol  = (tid & 31) << 2;   // 0..124

    const float* Ap  = A + (size_t)(bm + aRow) * K + aCol4 * 4;
    const float* Ap2 = Ap + (size_t)64 * K;
    const float* Bp  = B + (size_t)bRow * N + bn + bCol;
    const float* Bp2 = Bp + (size_t)8 * N;

    const int tx = (tid & 15) << 3;      // output col offset in tile
    const int ty = (tid >> 4) << 3;      // output row offset in tile

    float acc[8][8];
#pragma unroll
    for (int i = 0; i < 8; ++i)
#pragma unroll
        for (int j = 0; j < 8; ++j) acc[i][j] = 0.f;

    float4 pa0 = *(const float4*)Ap;
    float4 pa1 = *(const float4*)Ap2;
    float4 pb0 = *(const float4*)Bp;
    float4 pb1 = *(const float4*)Bp2;

    for (int k0 = 0; k0 < K; k0 += 16) {
        As[aCol4*4+0][aRow]    = pa0.x;
        As[aCol4*4+1][aRow]    = pa0.y;
        As[aCol4*4+2][aRow]    = pa0.z;
        As[aCol4*4+3][aRow]    = pa0.w;
        As[aCol4*4+0][aRow+64] = pa1.x;
        As[aCol4*4+1][aRow+64] = pa1.y;
        As[aCol4*4+2][aRow+64] = pa1.z;
        As[aCol4*4+3][aRow+64] = pa1.w;
        *(float4*)&Bs[bRow][bCol]   = pb0;
        *(float4*)&Bs[bRow+8][bCol] = pb1;
        __syncthreads();

        if (k0 + 16 < K) {  // prefetch next tile while computing this one
            pa0 = *(const float4*)(Ap  + k0 + 16);
            pa1 = *(const float4*)(Ap2 + k0 + 16);
            pb0 = *(const float4*)(Bp  + (size_t)(k0 + 16) * N);
            pb1 = *(const float4*)(Bp2 + (size_t)(k0 + 16) * N);
        }

#pragma unroll
        for (int k = 0; k < 16; ++k) {
            float ar[8], br[8];
            *(float4*)&ar[0] = *(const float4*)&As[k][ty];
            *(float4*)&ar[4] = *(const float4*)&As[k][ty + 4];
            *(float4*)&br[0] = *(const float4*)&Bs[k][tx];
            *(float4*)&br[4] = *(const float4*)&Bs[k][tx + 4];
#pragma unroll
            for (int i = 0; i < 8; ++i)
#pragma unroll
                for (int j = 0; j < 8; ++j)
                    acc[i][j] = fmaf(ar[i], br[j], acc[i][j]);
        }
        __syncthreads();
    }

    float* Cp = C + (size_t)(bm + ty) * N + bn + tx;
#pragma unroll
    for (int i = 0; i < 8; ++i) {
        *(float4*)(Cp + (size_t)i * N)     = make_float4(acc[i][0], acc[i][1], acc[i][2], acc[i][3]);
        *(float4*)(Cp + (size_t)i * N + 4) = make_float4(acc[i][4], acc[i][5], acc[i][6], acc[i][7]);
    }
}

// ============================================================================
// Depthwise causal conv (k=4) over L + bias + SiLU on the x_ half of xz.
// ============================================================================
__global__ __launch_bounds__(256) void conv_silu_k(
    const float* __restrict__ xz, const float* __restrict__ cw,
    const float* __restrict__ cb, float* __restrict__ xs)
{
    int idx = blockIdx.x * 256 + threadIdx.x;   // < NROWS*DINNER
    int d   = idx & (DINNER - 1);
    int row = idx >> 11;                        // DINNER = 2048 = 2^11
    int l   = row & (LSEQ - 1);

    float acc = cb[d];
#pragma unroll
    for (int k = 0; k < 4; ++k) {
        int ls = l - 3 + k;
        float xv = (ls >= 0) ? xz[(size_t)(row - 3 + k) * XZW + d] : 0.f;
        acc = fmaf(cw[d * 4 + k], xv, acc);
    }
    // SiLU
    xs[(size_t)row * DINNER + d] = acc / (1.f + __expf(-acc));
}

// ============================================================================
// bcd = xs @ W_x  (K=2048, N=33) -> split into B (0..15), C (16..31), delta(32)
// Block: 32 token rows, 256 threads; warp g owns n = g*4..g*4+3 (+ n=32 on g0)
// ============================================================================
__global__ __launch_bounds__(256) void bcd_k(
    const float* __restrict__ xs, const float* __restrict__ Wx,
    float* __restrict__ gB, float* __restrict__ gC, float* __restrict__ gdelta)
{
    __shared__ float sX[32 * 33];   // [k][row], pad 33
    __shared__ float sW[32 * 36];   // [k][n],  pad 36 (keeps float4 alignment)

    const int tid  = threadIdx.x;
    const int row0 = blockIdx.x * 32;
    const int row  = tid & 31;
    const int g    = tid >> 5;      // warp id 0..7

    float acc0 = 0.f, acc1 = 0.f, acc2 = 0.f, acc3 = 0.f, accd = 0.f;

    for (int kc = 0; kc < DINNER; kc += 32) {
        for (int e = tid; e < 32 * 36; e += 256) {
            int k = e / 36, n = e - k * 36;
            sW[e] = (n < 33) ? Wx[(size_t)(kc + k) * 33 + n] : 0.f;
        }
        {
            int r = tid >> 3, c4 = tid & 7;
            float4 v = *(const float4*)(xs + (size_t)(row0 + r) * DINNER + kc + c4 * 4);
            int kk = c4 * 4;
            sX[(kk + 0) * 33 + r] = v.x;
            sX[(kk + 1) * 33 + r] = v.y;
            sX[(kk + 2) * 33 + r] = v.z;
            sX[(kk + 3) * 33 + r] = v.w;
        }
        __syncthreads();
#pragma unroll 8
        for (int k = 0; k < 32; ++k) {
            float  xv = sX[k * 33 + row];
            float4 wv = *(const float4*)(&sW[k * 36 + g * 4]);
            acc0 = fmaf(xv, wv.x, acc0);
            acc1 = fmaf(xv, wv.y, acc1);
            acc2 = fmaf(xv, wv.z, acc2);
            acc3 = fmaf(xv, wv.w, acc3);
            if (g == 0) accd = fmaf(xv, sW[k * 36 + 32], accd);
        }
        __syncthreads();
    }

    const int grow = row0 + row;
    float a[4] = {acc0, acc1, acc2, acc3};
#pragma unroll
    for (int j = 0; j < 4; ++j) {
        int nn = g * 4 + j;
        if (nn < 16) gB[(size_t)grow * 16 + nn]        = a[j];
        else         gC[(size_t)grow * 16 + (nn - 16)] = a[j];
    }
    if (g == 0) gdelta[grow] = accd;
}

// ============================================================================
// dt = softplus(delta * w_dt + b_dt)   — precomputed so the scan does 1 exp/step
// ============================================================================
__global__ __launch_bounds__(256) void dt_k(
    const float* __restrict__ gdelta, const float* __restrict__ w_dt,
    const float* __restrict__ b_dt, float* __restrict__ gdt)
{
    int idx = blockIdx.x * 256 + threadIdx.x;
    int d   = idx & (DINNER - 1);
    int row = idx >> 11;
    float v = fmaf(gdelta[row], w_dt[d], b_dt[d]);
    gdt[idx] = (v > 30.f) ? v : log1pf(__expf(v));
}

// ============================================================================
// Selective scan, fused with skip (+x*Dp) and gate (*silu(z)).
// Block = one batch b, 16 channels d0..d0+15, full L. 8 warps, 2 chains/warp,
// 16 lanes per chain (one state per lane), shfl-xor reduce for y.
// ============================================================================
__global__ __launch_bounds__(256) void scan_k(
    const float* __restrict__ gdt, const float* __restrict__ gxs,
    const float* __restrict__ gxz, const float* __restrict__ gB,
    const float* __restrict__ gC,  const float* __restrict__ A_log,
    const float* __restrict__ Dp,  float* __restrict__ gyz)
{
    __shared__ float sB [64 * 16];
    __shared__ float sC [64 * 16];
    __shared__ float sdt[64 * 16];
    __shared__ float sx [64 * 16];
    __shared__ float sz [64 * 16];
    __shared__ float sy [64 * 16];

    const int tid  = threadIdx.x;
    const int lane = tid & 31;
    const int w    = tid >> 5;            // 0..7
    const int cidx = 2 * w + (lane >> 4); // chain 0..15 within block
    const int n    = lane & 15;           // state index
    const int b    = blockIdx.x >> 7;     // 0..1
    const int d0   = (blockIdx.x & 127) * 16;
    const int d    = d0 + cidx;

    const float A  = -expf(A_log[d * DSTATE + n]);
    const float dp = Dp[d];
    float h = 0.f;

    for (int t0 = 0; t0 < LSEQ; t0 += 64) {
        // ---- stage tiles ----
        {
            size_t base_bc = (size_t)(b * LSEQ + t0) * DSTATE;  // 1024 contiguous floats
            ((float4*)sB)[tid] = ((const float4*)(gB + base_bc))[tid];
            ((float4*)sC)[tid] = ((const float4*)(gC + base_bc))[tid];
#pragma unroll
            for (int i = 0; i < 4; ++i) {
                int e  = tid + i * 256;
                int l  = e >> 4, dd = e & 15;
                size_t grow = (size_t)(b * LSEQ + t0 + l);
                sdt[e] = gdt[grow * DINNER + d0 + dd];
                sx[e]  = gxs[grow * DINNER + d0 + dd];
                sz[e]  = gxz[grow * XZW + DINNER + d0 + dd];
            }
        }
        __syncthreads();

        // ---- 64 sequential steps ----
        for (int l = 0; l < 64; ++l) {
            float dt = sdt[l * 16 + cidx];
            float xv = sx [l * 16 + cidx];
            float a  = __expf(dt * A);
            h = fmaf(a, h, dt * xv * sB[l * 16 + n]);
            float p = h * sC[l * 16 + n];
            p += __shfl_xor_sync(0xffffffffu, p, 8);
            p += __shfl_xor_sync(0xffffffffu, p, 4);
            p += __shfl_xor_sync(0xffffffffu, p, 2);
            p += __shfl_xor_sync(0xffffffffu, p, 1);
            if (n == 0) {
                float y  = fmaf(xv, dp, p);
                float zv = sz[l * 16 + cidx];
                sy[l * 16 + cidx] = y * (zv / (1.f + __expf(-zv)));
            }
        }
        __syncthreads();

        // ---- coalesced store of the gated output tile ----
#pragma unroll
        for (int i = 0; i < 4; ++i) {
            int e  = tid + i * 256;
            int l  = e >> 4, dd = e & 15;
            size_t grow = (size_t)(b * LSEQ + t0 + l);
            gyz[grow * DINNER + d0 + dd] = sy[e];
        }
        __syncthreads();
    }
}

// ============================================================================
// launch
// ============================================================================
extern "C" void kernel_launch(void* const* d_in, const int* in_sizes, int n_in,
                              void* d_out, int out_size)
{
    const float* x     = (const float*)d_in[0];
    const float* W_in  = (const float*)d_in[1];
    const float* convw = (const float*)d_in[2];
    const float* convb = (const float*)d_in[3];
    const float* W_x   = (const float*)d_in[4];
    const float* w_dt  = (const float*)d_in[5];
    const float* b_dt  = (const float*)d_in[6];
    const float* A_log = (const float*)d_in[7];
    const float* Dp    = (const float*)d_in[8];
    const float* W_out = (const float*)d_in[9];
    float* out = (float*)d_out;

    float *p_xz, *p_xs, *p_dt, *p_yz, *p_B, *p_C, *p_delta;
    cudaGetSymbolAddress((void**)&p_xz,    g_xz);
    cudaGetSymbolAddress((void**)&p_xs,    g_xs);
    cudaGetSymbolAddress((void**)&p_dt,    g_dt);
    cudaGetSymbolAddress((void**)&p_yz,    g_yz);
    cudaGetSymbolAddress((void**)&p_B,     g_Bc);
    cudaGetSymbolAddress((void**)&p_C,     g_Cc);
    cudaGetSymbolAddress((void**)&p_delta, g_delta);

    // 1. xz = x @ W_in            [4096,1024]@[1024,4096]
    sgemm_k<<<dim3(XZW / 128, NROWS / 128), 256>>>(x, W_in, p_xz, NROWS, XZW, DMODEL);

    // 2. xs = silu(conv(x_) + b)
    conv_silu_k<<<(NROWS * DINNER) / 256, 256>>>(p_xz, convw, convb, p_xs);

    // 3. B, C, delta = xs @ W_x
    bcd_k<<<NROWS / 32, 256>>>(p_xs, W_x, p_B, p_C, p_delta);

    // 4. dt = softplus(delta * w_dt + b_dt)
    dt_k<<<(NROWS * DINNER) / 256, 256>>>(p_delta, w_dt, b_dt, p_dt);

    // 5. selective scan + skip + gate -> yz
    scan_k<<<BATCH * (DINNER / 16), 256>>>(p_dt, p_xs, p_xz, p_B, p_C, A_log, Dp, p_yz);

    // 6. out = yz @ W_out          [4096,2048]@[2048,1024]
    sgemm_k<<<dim3(DMODEL / 128, NROWS / 128), 256>>>(p_yz, W_out, out, NROWS, DMODEL, DINNER);
}

// round 6
// speedup vs baseline: 1.5326x; 1.5326x over previous
#include <cuda_runtime.h>
#include <cuda_bf16.h>
#include <cstdint>
#include <cmath>

// Problem constants
#define BATCH   2
#define LSEQ    2048
#define DMODEL  1024
#define DINNER  2048
#define DSTATE  16
#define NROWS   (BATCH*LSEQ)          // 4096
#define XZW     (2*DINNER)            // 4096

// ---------------- scratch (static device arrays; no allocation) ------------
__device__ float g_xz   [(size_t)NROWS * XZW];     // x@W_in (x_|z)
__device__ float g_xs   [(size_t)NROWS * DINNER];  // silu(conv(x_))
__device__ float g_Bc   [(size_t)NROWS * DSTATE];
__device__ float g_Cc   [(size_t)NROWS * DSTATE];
__device__ float g_delta[NROWS];

// bf16 split operands for tensor-core GEMMs (aligned for 16B cp.async)
__device__ __align__(128) __nv_bfloat16 g_xa_h[(size_t)NROWS * DMODEL];
__device__ __align__(128) __nv_bfloat16 g_xa_l[(size_t)NROWS * DMODEL];
__device__ __align__(128) __nv_bfloat16 g_w1_h[(size_t)XZW * DMODEL];     // W_in^T  [4096,1024]
__device__ __align__(128) __nv_bfloat16 g_w1_l[(size_t)XZW * DMODEL];
__device__ __align__(128) __nv_bfloat16 g_ya_h[(size_t)NROWS * DINNER];
__device__ __align__(128) __nv_bfloat16 g_ya_l[(size_t)NROWS * DINNER];
__device__ __align__(128) __nv_bfloat16 g_w2_h[(size_t)DMODEL * DINNER];  // W_out^T [1024,2048]
__device__ __align__(128) __nv_bfloat16 g_w2_l[(size_t)DMODEL * DINNER];

// ============================ PTX helpers (sm_100-safe) =====================
__device__ __forceinline__ uint32_t smem_u32(const void* p) {
    uint32_t a;
    asm("{ .reg .u64 t; cvta.to.shared.u64 t, %1; cvt.u32.u64 %0, t; }" : "=r"(a) : "l"(p));
    return a;
}
__device__ __forceinline__ void cp16(uint32_t dst, const void* src) {
    asm volatile("cp.async.cg.shared.global [%0], [%1], 16;" :: "r"(dst), "l"(src));
}
__device__ __forceinline__ void cp_commit() {
    asm volatile("cp.async.commit_group;" ::: "memory");
}
__device__ __forceinline__ void ldsm4(uint32_t* r, uint32_t a) {
    asm volatile("ldmatrix.sync.aligned.m8n8.x4.shared.b16 {%0,%1,%2,%3}, [%4];"
        : "=r"(r[0]), "=r"(r[1]), "=r"(r[2]), "=r"(r[3]) : "r"(a));
}
__device__ __forceinline__ void mma16816(float* d, const uint32_t* a, uint32_t b0, uint32_t b1) {
    asm volatile("mma.sync.aligned.m16n8k16.row.col.f32.bf16.bf16.f32 "
        "{%0,%1,%2,%3},{%4,%5,%6,%7},{%8,%9},{%0,%1,%2,%3};"
        : "+f"(d[0]), "+f"(d[1]), "+f"(d[2]), "+f"(d[3])
        : "r"(a[0]), "r"(a[1]), "r"(a[2]), "r"(a[3]), "r"(b0), "r"(b1));
}

// ============================================================================
// Tensor-core GEMM via warp mma.sync:  C[M,N] = A[M,K] @ B^T
// A row-major [M,K] hi/lo bf16; B K-major [N,K] hi/lo bf16 (weights pre-T).
// CTA 128x128, K chunks of 64 (SW128 rows, seg^row&7 swizzle), cp.async
// double-buffer, 8 warps (4m x 2n), warp tile 32x64, 3-term split accum.
// ============================================================================
__global__ __launch_bounds__(256) void gemm_mma(
    const __nv_bfloat16* __restrict__ Ah, const __nv_bfloat16* __restrict__ Al,
    const __nv_bfloat16* __restrict__ Bh, const __nv_bfloat16* __restrict__ Bl,
    float* __restrict__ C, int M, int N, int K)
{
    extern __shared__ char smem[];
    const uint32_t sb = smem_u32(smem);

    const int tid  = threadIdx.x;
    const int lane = tid & 31, wid = tid >> 5;
    const int wm   = wid >> 1, wn = wid & 1;
    const int m0   = blockIdx.y * 128, n0 = blockIdx.x * 128;
    const int NC   = K >> 6;

    const int lrow0 = tid >> 3;   // 0..31 (loader)
    const int lseg  = tid & 7;
    const int lr    = lane & 15;  // ldmatrix row-in-tile
    const int lc    = lane >> 4;  // ldmatrix col16 half

    float acc[2][8][4];
#pragma unroll
    for (int i = 0; i < 2; ++i)
#pragma unroll
        for (int j = 0; j < 8; ++j)
#pragma unroll
            for (int q = 0; q < 4; ++q) acc[i][j][q] = 0.f;

    // issue one chunk's cp.async loads (4 tiles x 16KB) into buffer c&1
    auto LOAD = [&](int c) {
        const int kc = c << 6;
        const uint32_t base = sb + (uint32_t)(c & 1) * 65536u;
#pragma unroll
        for (int i = 0; i < 4; ++i) {
            int row = lrow0 + i * 32;
            uint32_t sw = (uint32_t)((lseg ^ (row & 7)) << 4);
            uint32_t ro = (uint32_t)row * 128u + sw;
            cp16(base + ro,          Ah + (size_t)(m0 + row) * K + kc + lseg * 8);
            cp16(base + 16384u + ro, Al + (size_t)(m0 + row) * K + kc + lseg * 8);
            cp16(base + 32768u + ro, Bh + (size_t)(n0 + row) * K + kc + lseg * 8);
            cp16(base + 49152u + ro, Bl + (size_t)(n0 + row) * K + kc + lseg * 8);
        }
        cp_commit();
    };

    for (int c = 0; c < NC; ++c) {
        if (c == 0) { LOAD(0); if (NC > 1) LOAD(1); }
        else if (c + 1 < NC) LOAD(c + 1);

        if (c + 1 < NC) asm volatile("cp.async.wait_group 1;" ::: "memory");
        else            asm volatile("cp.async.wait_group 0;" ::: "memory");
        __syncthreads();

        const uint32_t ab = sb + (uint32_t)(c & 1) * 65536u;
        const uint32_t bb = ab + 32768u;

#pragma unroll
        for (int ks = 0; ks < 4; ++ks) {
            uint32_t ah[2][4], al[2][4], bh[4][4], bl[4][4];
#pragma unroll
            for (int am = 0; am < 2; ++am) {
                int row = wm * 32 + am * 16 + lr;
                uint32_t c16 = (uint32_t)((ks * 2 + lc) ^ (row & 7));
                uint32_t off = (uint32_t)row * 128u + (c16 << 4);
                ldsm4(ah[am], ab + off);
                ldsm4(al[am], ab + 16384u + off);
            }
#pragma unroll
            for (int nb = 0; nb < 4; ++nb) {
                int row = wn * 64 + nb * 16 + lr;
                uint32_t c16 = (uint32_t)((ks * 2 + lc) ^ (row & 7));
                uint32_t off = (uint32_t)row * 128u + (c16 << 4);
                ldsm4(bh[nb], bb + off);
                ldsm4(bl[nb], bb + 16384u + off);
            }
#pragma unroll
            for (int am = 0; am < 2; ++am)
#pragma unroll
                for (int nb = 0; nb < 4; ++nb)
#pragma unroll
                    for (int h2 = 0; h2 < 2; ++h2) {
                        float* d = acc[am][nb * 2 + h2];
                        mma16816(d, ah[am], bh[nb][h2], bh[nb][h2 + 2]);
                        mma16816(d, ah[am], bl[nb][h2], bl[nb][h2 + 2]);
                        mma16816(d, al[am], bh[nb][h2], bh[nb][h2 + 2]);
                    }
        }
        __syncthreads();
    }

    // epilogue: direct float2 stores
    const int er = lane >> 2, ec = (lane & 3) * 2;
#pragma unroll
    for (int am = 0; am < 2; ++am) {
        int row = m0 + wm * 32 + am * 16 + er;
#pragma unroll
        for (int na = 0; na < 8; ++na) {
            int col = n0 + wn * 64 + na * 8 + ec;
            float* d = acc[am][na];
            *reinterpret_cast<float2*>(C + (size_t)row * N + col)       = make_float2(d[0], d[1]);
            *reinterpret_cast<float2*>(C + (size_t)(row + 8) * N + col) = make_float2(d[2], d[3]);
        }
    }
}

// ============================================================================
// fp32 -> (hi,lo) bf16 split, elementwise (x4 vectorized)
// ============================================================================
__global__ __launch_bounds__(256) void split_bf16_k(
    const float* __restrict__ in, __nv_bfloat16* __restrict__ hi,
    __nv_bfloat16* __restrict__ lo, int n4)
{
    int i = blockIdx.x * 256 + threadIdx.x;
    if (i >= n4) return;
    float4 v = reinterpret_cast<const float4*>(in)[i];
    __nv_bfloat16 h0 = __float2bfloat16(v.x), h1 = __float2bfloat16(v.y);
    __nv_bfloat16 h2 = __float2bfloat16(v.z), h3 = __float2bfloat16(v.w);
    reinterpret_cast<__nv_bfloat162*>(hi)[2 * i]     = __halves2bfloat162(h0, h1);
    reinterpret_cast<__nv_bfloat162*>(hi)[2 * i + 1] = __halves2bfloat162(h2, h3);
    __nv_bfloat16 l0 = __float2bfloat16(v.x - __bfloat162float(h0));
    __nv_bfloat16 l1 = __float2bfloat16(v.y - __bfloat162float(h1));
    __nv_bfloat16 l2 = __float2bfloat16(v.z - __bfloat162float(h2));
    __nv_bfloat16 l3 = __float2bfloat16(v.w - __bfloat162float(h3));
    reinterpret_cast<__nv_bfloat162*>(lo)[2 * i]     = __halves2bfloat162(l0, l1);
    reinterpret_cast<__nv_bfloat162*>(lo)[2 * i + 1] = __halves2bfloat162(l2, l3);
}

// ============================================================================
// W[K,N] fp32 -> Wt hi/lo [N,K] bf16 (transpose + split)
// ============================================================================
__global__ __launch_bounds__(256) void tr_split_k(
    const float* __restrict__ W, __nv_bfloat16* __restrict__ hi,
    __nv_bfloat16* __restrict__ lo, int K, int N)
{
    __shared__ float t[32][33];
    const int k0 = blockIdx.y * 32, n0 = blockIdx.x * 32;
    const int tx = threadIdx.x & 31, ty = threadIdx.x >> 5;
#pragma unroll
    for (int i = 0; i < 4; ++i)
        t[ty + i * 8][tx] = W[(size_t)(k0 + ty + i * 8) * N + n0 + tx];
    __syncthreads();
#pragma unroll
    for (int i = 0; i < 4; ++i) {
        int n = n0 + ty + i * 8;
        float v = t[tx][ty + i * 8];
        __nv_bfloat16 h = __float2bfloat16(v);
        hi[(size_t)n * K + k0 + tx] = h;
        lo[(size_t)n * K + k0 + tx] = __float2bfloat16(v - __bfloat162float(h));
    }
}

// ============================================================================
// Depthwise causal conv (k=4) + bias + SiLU on x_ half of xz
// ============================================================================
__global__ __launch_bounds__(256) void conv_silu_k(
    const float* __restrict__ xz, const float* __restrict__ cw,
    const float* __restrict__ cb, float* __restrict__ xs)
{
    int idx = blockIdx.x * 256 + threadIdx.x;
    int d   = idx & (DINNER - 1);
    int row = idx >> 11;
    int l   = row & (LSEQ - 1);

    float acc = cb[d];
#pragma unroll
    for (int k = 0; k < 4; ++k) {
        int ls = l - 3 + k;
        float xv = (ls >= 0) ? xz[(size_t)(row - 3 + k) * XZW + d] : 0.f;
        acc = fmaf(cw[d * 4 + k], xv, acc);
    }
    xs[(size_t)row * DINNER + d] = acc / (1.f + __expf(-acc));
}

// ============================================================================
// bcd = xs @ W_x  (K=2048, N=33) -> B, C, delta
// ============================================================================
__global__ __launch_bounds__(256) void bcd_k(
    const float* __restrict__ xs, const float* __restrict__ Wx,
    float* __restrict__ gB, float* __restrict__ gC, float* __restrict__ gdelta)
{
    __shared__ float sX[32 * 33];
    __shared__ float sW[32 * 36];

    const int tid  = threadIdx.x;
    const int row0 = blockIdx.x * 32;
    const int row  = tid & 31;
    const int g    = tid >> 5;

    float acc0 = 0.f, acc1 = 0.f, acc2 = 0.f, acc3 = 0.f, accd = 0.f;

    for (int kc = 0; kc < DINNER; kc += 32) {
        for (int e = tid; e < 32 * 36; e += 256) {
            int k = e / 36, n = e - k * 36;
            sW[e] = (n < 33) ? Wx[(size_t)(kc + k) * 33 + n] : 0.f;
        }
        {
            int r = tid >> 3, c4 = tid & 7;
            float4 v = *(const float4*)(xs + (size_t)(row0 + r) * DINNER + kc + c4 * 4);
            int kk = c4 * 4;
            sX[(kk + 0) * 33 + r] = v.x;
            sX[(kk + 1) * 33 + r] = v.y;
            sX[(kk + 2) * 33 + r] = v.z;
            sX[(kk + 3) * 33 + r] = v.w;
        }
        __syncthreads();
#pragma unroll 8
        for (int k = 0; k < 32; ++k) {
            float  xv = sX[k * 33 + row];
            float4 wv = *(const float4*)(&sW[k * 36 + g * 4]);
            acc0 = fmaf(xv, wv.x, acc0);
            acc1 = fmaf(xv, wv.y, acc1);
            acc2 = fmaf(xv, wv.z, acc2);
            acc3 = fmaf(xv, wv.w, acc3);
            if (g == 0) accd = fmaf(xv, sW[k * 36 + 32], accd);
        }
        __syncthreads();
    }

    const int grow = row0 + row;
    float a[4] = {acc0, acc1, acc2, acc3};
#pragma unroll
    for (int j = 0; j < 4; ++j) {
        int nn = g * 4 + j;
        if (nn < 16) gB[(size_t)grow * 16 + nn]        = a[j];
        else         gC[(size_t)grow * 16 + (nn - 16)] = a[j];
    }
    if (g == 0) gdelta[grow] = accd;
}

// ============================================================================
// Selective scan + skip + gate, with fused softplus(dt) and fused bf16
// hi/lo split of the gated output (feeds GEMM2 directly).
// ============================================================================
__global__ __launch_bounds__(256) void scan_k(
    const float* __restrict__ gdelta, const float* __restrict__ w_dt,
    const float* __restrict__ b_dt,
    const float* __restrict__ gxs,  const float* __restrict__ gxz,
    const float* __restrict__ gB,   const float* __restrict__ gC,
    const float* __restrict__ A_log, const float* __restrict__ Dp,
    __nv_bfloat16* __restrict__ yh, __nv_bfloat16* __restrict__ yl)
{
    __shared__ float sB [64 * 16];
    __shared__ float sC [64 * 16];
    __shared__ float sdt[64 * 16];
    __shared__ float sx [64 * 16];
    __shared__ float sz [64 * 16];
    __shared__ float sy [64 * 16];

    const int tid  = threadIdx.x;
    const int lane = tid & 31;
    const int w    = tid >> 5;
    const int cidx = 2 * w + (lane >> 4);
    const int n    = lane & 15;
    const int b    = blockIdx.x >> 7;
    const int d0   = (blockIdx.x & 127) * 16;
    const int d    = d0 + cidx;

    const float A  = -expf(A_log[d * DSTATE + n]);
    const float dp = Dp[d];
    float h = 0.f;

    for (int t0 = 0; t0 < LSEQ; t0 += 64) {
        {
            size_t base_bc = (size_t)(b * LSEQ + t0) * DSTATE;
            ((float4*)sB)[tid] = ((const float4*)(gB + base_bc))[tid];
            ((float4*)sC)[tid] = ((const float4*)(gC + base_bc))[tid];
#pragma unroll
            for (int i = 0; i < 4; ++i) {
                int e  = tid + i * 256;
                int l  = e >> 4, dd = e & 15;
                size_t grow = (size_t)(b * LSEQ + t0 + l);
                int dg = d0 + dd;
                float v = fmaf(gdelta[grow], w_dt[dg], b_dt[dg]);
                sdt[e] = (v > 30.f) ? v : log1pf(__expf(v));
                sx[e]  = gxs[grow * DINNER + dg];
                sz[e]  = gxz[grow * XZW + DINNER + dg];
            }
        }
        __syncthreads();

        for (int l = 0; l < 64; ++l) {
            float dt = sdt[l * 16 + cidx];
            float xv = sx [l * 16 + cidx];
            float a  = __expf(dt * A);
            h = fmaf(a, h, dt * xv * sB[l * 16 + n]);
            float p = h * sC[l * 16 + n];
            p += __shfl_xor_sync(0xffffffffu, p, 8);
            p += __shfl_xor_sync(0xffffffffu, p, 4);
            p += __shfl_xor_sync(0xffffffffu, p, 2);
            p += __shfl_xor_sync(0xffffffffu, p, 1);
            if (n == 0) {
                float y  = fmaf(xv, dp, p);
                float zv = sz[l * 16 + cidx];
                sy[l * 16 + cidx] = y * (zv / (1.f + __expf(-zv)));
            }
        }
        __syncthreads();

#pragma unroll
        for (int i = 0; i < 4; ++i) {
            int e  = tid + i * 256;
            int l  = e >> 4, dd = e & 15;
            size_t grow = (size_t)(b * LSEQ + t0 + l);
            float v = sy[e];
            __nv_bfloat16 hv = __float2bfloat16(v);
            yh[grow * DINNER + d0 + dd] = hv;
            yl[grow * DINNER + d0 + dd] = __float2bfloat16(v - __bfloat162float(hv));
        }
        __syncthreads();
    }
}

// ============================================================================
// launch
// ============================================================================
extern "C" void kernel_launch(void* const* d_in, const int* in_sizes, int n_in,
                              void* d_out, int out_size)
{
    const float* x     = (const float*)d_in[0];
    const float* W_in  = (const float*)d_in[1];
    const float* convw = (const float*)d_in[2];
    const float* convb = (const float*)d_in[3];
    const float* W_x   = (const float*)d_in[4];
    const float* w_dt  = (const float*)d_in[5];
    const float* b_dt  = (const float*)d_in[6];
    const float* A_log = (const float*)d_in[7];
    const float* Dp    = (const float*)d_in[8];
    const float* W_out = (const float*)d_in[9];
    float* out = (float*)d_out;

    float *p_xz, *p_xs, *p_B, *p_C, *p_delta;
    cudaGetSymbolAddress((void**)&p_xz,    g_xz);
    cudaGetSymbolAddress((void**)&p_xs,    g_xs);
    cudaGetSymbolAddress((void**)&p_B,     g_Bc);
    cudaGetSymbolAddress((void**)&p_C,     g_Cc);
    cudaGetSymbolAddress((void**)&p_delta, g_delta);

    __nv_bfloat16 *xa_h, *xa_l, *w1_h, *w1_l, *ya_h, *ya_l, *w2_h, *w2_l;
    cudaGetSymbolAddress((void**)&xa_h, g_xa_h);
    cudaGetSymbolAddress((void**)&xa_l, g_xa_l);
    cudaGetSymbolAddress((void**)&w1_h, g_w1_h);
    cudaGetSymbolAddress((void**)&w1_l, g_w1_l);
    cudaGetSymbolAddress((void**)&ya_h, g_ya_h);
    cudaGetSymbolAddress((void**)&ya_l, g_ya_l);
    cudaGetSymbolAddress((void**)&w2_h, g_w2_h);
    cudaGetSymbolAddress((void**)&w2_l, g_w2_l);

    constexpr int GSMEM = 131072;   // 2 bufs x (4 tiles x 16KB)
    cudaFuncSetAttribute((const void*)gemm_mma,
                         cudaFuncAttributeMaxDynamicSharedMemorySize, GSMEM);

    // prep: weight transpose+split, x split
    tr_split_k<<<dim3(XZW / 32, DMODEL / 32), 256>>>(W_in, w1_h, w1_l, DMODEL, XZW);
    tr_split_k<<<dim3(DMODEL / 32, DINNER / 32), 256>>>(W_out, w2_h, w2_l, DINNER, DMODEL);
    split_bf16_k<<<(NROWS * DMODEL / 4 + 255) / 256, 256>>>(x, xa_h, xa_l, NROWS * DMODEL / 4);

    // 1. xz = x @ W_in  (mma.sync bf16-split)
    gemm_mma<<<dim3(XZW / 128, NROWS / 128), 256, GSMEM>>>(
        xa_h, xa_l, w1_h, w1_l, p_xz, NROWS, XZW, DMODEL);

    // 2. xs = silu(conv(x_) + b)
    conv_silu_k<<<(NROWS * DINNER) / 256, 256>>>(p_xz, convw, convb, p_xs);

    // 3. B, C, delta
    bcd_k<<<NROWS / 32, 256>>>(p_xs, W_x, p_B, p_C, p_delta);

    // 4+5. selective scan (fused softplus, skip, gate, bf16 split)
    scan_k<<<BATCH * (DINNER / 16), 256>>>(
        p_delta, w_dt, b_dt, p_xs, p_xz, p_B, p_C, A_log, Dp, ya_h, ya_l);

    // 6. out = yz @ W_out  (mma.sync bf16-split)
    gemm_mma<<<dim3(DMODEL / 128, NROWS / 128), 256, GSMEM>>>(
        ya_h, ya_l, w2_h, w2_l, out, NROWS, DMODEL, DINNER);
}

// round 7
// speedup vs baseline: 2.0377x; 1.3295x over previous
#include <cuda_runtime.h>
#include <cuda_bf16.h>
#include <cstdint>
#include <cmath>

// Problem constants
#define BATCH   2
#define LSEQ    2048
#define DMODEL  1024
#define DINNER  2048
#define DSTATE  16
#define NROWS   (BATCH*LSEQ)          // 4096
#define XZW     (2*DINNER)            // 4096

// ---------------- scratch (static device arrays; no allocation) ------------
__device__ float g_xz   [(size_t)NROWS * XZW];     // x@W_in (x_|z)
__device__ float g_xs   [(size_t)NROWS * DINNER];  // silu(conv(x_))
__device__ float g_Bc   [(size_t)NROWS * DSTATE];
__device__ float g_Cc   [(size_t)NROWS * DSTATE];
__device__ float g_delta[NROWS];

// bf16 split operands for tensor-core GEMMs (aligned for 16B cp.async)
__device__ __align__(128) __nv_bfloat16 g_xa_h[(size_t)NROWS * DMODEL];
__device__ __align__(128) __nv_bfloat16 g_xa_l[(size_t)NROWS * DMODEL];
__device__ __align__(128) __nv_bfloat16 g_w1_h[(size_t)XZW * DMODEL];     // W_in^T  [4096,1024]
__device__ __align__(128) __nv_bfloat16 g_w1_l[(size_t)XZW * DMODEL];
__device__ __align__(128) __nv_bfloat16 g_ya_h[(size_t)NROWS * DINNER];
__device__ __align__(128) __nv_bfloat16 g_ya_l[(size_t)NROWS * DINNER];
__device__ __align__(128) __nv_bfloat16 g_w2_h[(size_t)DMODEL * DINNER];  // W_out^T [1024,2048]
__device__ __align__(128) __nv_bfloat16 g_w2_l[(size_t)DMODEL * DINNER];

// ============================ PTX helpers (sm_100-safe) =====================
__device__ __forceinline__ uint32_t smem_u32(const void* p) {
    uint32_t a;
    asm("{ .reg .u64 t; cvta.to.shared.u64 t, %1; cvt.u32.u64 %0, t; }" : "=r"(a) : "l"(p));
    return a;
}
__device__ __forceinline__ void cp16(uint32_t dst, const void* src) {
    asm volatile("cp.async.cg.shared.global [%0], [%1], 16;" :: "r"(dst), "l"(src));
}
__device__ __forceinline__ void cp_commit() {
    asm volatile("cp.async.commit_group;" ::: "memory");
}
__device__ __forceinline__ void ldsm4(uint32_t* r, uint32_t a) {
    asm volatile("ldmatrix.sync.aligned.m8n8.x4.shared.b16 {%0,%1,%2,%3}, [%4];"
        : "=r"(r[0]), "=r"(r[1]), "=r"(r[2]), "=r"(r[3]) : "r"(a));
}
__device__ __forceinline__ void mma16816(float* d, const uint32_t* a, uint32_t b0, uint32_t b1) {
    asm volatile("mma.sync.aligned.m16n8k16.row.col.f32.bf16.bf16.f32 "
        "{%0,%1,%2,%3},{%4,%5,%6,%7},{%8,%9},{%0,%1,%2,%3};"
        : "+f"(d[0]), "+f"(d[1]), "+f"(d[2]), "+f"(d[3])
        : "r"(a[0]), "r"(a[1]), "r"(a[2]), "r"(a[3]), "r"(b0), "r"(b1));
}

// ============================================================================
// Tensor-core GEMM via warp mma.sync:  C[M,N] = A[M,K] @ B^T
// A row-major [M,K] hi/lo bf16; B K-major [N,K] hi/lo bf16 (weights pre-T).
// CTA 128x128, K chunks of 64, 3-STAGE cp.async pipeline (192 KB smem),
// one __syncthreads per chunk. 8 warps (4m x 2n), warp tile 32x64,
// 3-term bf16 split accumulation.
// ============================================================================
#define STAGE_BYTES 65536u

__global__ __launch_bounds__(256) void gemm_mma(
    const __nv_bfloat16* __restrict__ Ah, const __nv_bfloat16* __restrict__ Al,
    const __nv_bfloat16* __restrict__ Bh, const __nv_bfloat16* __restrict__ Bl,
    float* __restrict__ C, int M, int N, int K)
{
    extern __shared__ char smem[];
    const uint32_t sb = smem_u32(smem);

    const int tid  = threadIdx.x;
    const int lane = tid & 31, wid = tid >> 5;
    const int wm   = wid >> 1, wn = wid & 1;
    const int m0   = blockIdx.y * 128, n0 = blockIdx.x * 128;
    const int NC   = K >> 6;

    const int lrow0 = tid >> 3;   // 0..31 (loader)
    const int lseg  = tid & 7;
    const int lr    = lane & 15;  // ldmatrix row-in-tile
    const int lc    = lane >> 4;  // ldmatrix col16 half

    float acc[2][8][4];
#pragma unroll
    for (int i = 0; i < 2; ++i)
#pragma unroll
        for (int j = 0; j < 8; ++j)
#pragma unroll
            for (int q = 0; q < 4; ++q) acc[i][j][q] = 0.f;

    // issue one chunk's cp.async loads (4 tiles x 16KB) into stage c%3
    auto LOAD = [&](int c) {
        const int kc = c << 6;
        const uint32_t base = sb + (uint32_t)(c % 3) * STAGE_BYTES;
#pragma unroll
        for (int i = 0; i < 4; ++i) {
            int row = lrow0 + i * 32;
            uint32_t sw = (uint32_t)((lseg ^ (row & 7)) << 4);
            uint32_t ro = (uint32_t)row * 128u + sw;
            cp16(base + ro,          Ah + (size_t)(m0 + row) * K + kc + lseg * 8);
            cp16(base + 16384u + ro, Al + (size_t)(m0 + row) * K + kc + lseg * 8);
            cp16(base + 32768u + ro, Bh + (size_t)(n0 + row) * K + kc + lseg * 8);
            cp16(base + 49152u + ro, Bl + (size_t)(n0 + row) * K + kc + lseg * 8);
        }
        cp_commit();
    };

    LOAD(0);
    if (NC > 1) LOAD(1);

    for (int c = 0; c < NC; ++c) {
        // wait for group c (FIFO): <=1 pending normally, 0 on last chunk
        if (c + 1 < NC) asm volatile("cp.async.wait_group 1;" ::: "memory");
        else            asm volatile("cp.async.wait_group 0;" ::: "memory");
        __syncthreads();
        // stage (c+2)%3 == (c-1)%3: all threads finished chunk c-1 (barrier above)
        if (c + 2 < NC) LOAD(c + 2);

        const uint32_t ab = sb + (uint32_t)(c % 3) * STAGE_BYTES;
        const uint32_t bb = ab + 32768u;

#pragma unroll
        for (int ks = 0; ks < 4; ++ks) {
            uint32_t ah[2][4], al[2][4], bh[4][4], bl[4][4];
#pragma unroll
            for (int am = 0; am < 2; ++am) {
                int row = wm * 32 + am * 16 + lr;
                uint32_t c16 = (uint32_t)((ks * 2 + lc) ^ (row & 7));
                uint32_t off = (uint32_t)row * 128u + (c16 << 4);
                ldsm4(ah[am], ab + off);
                ldsm4(al[am], ab + 16384u + off);
            }
#pragma unroll
            for (int nb = 0; nb < 4; ++nb) {
                int row = wn * 64 + nb * 16 + lr;
                uint32_t c16 = (uint32_t)((ks * 2 + lc) ^ (row & 7));
                uint32_t off = (uint32_t)row * 128u + (c16 << 4);
                ldsm4(bh[nb], bb + off);
                ldsm4(bl[nb], bb + 16384u + off);
            }
#pragma unroll
            for (int am = 0; am < 2; ++am)
#pragma unroll
                for (int nb = 0; nb < 4; ++nb)
#pragma unroll
                    for (int h2 = 0; h2 < 2; ++h2) {
                        float* d = acc[am][nb * 2 + h2];
                        mma16816(d, ah[am], bh[nb][h2], bh[nb][h2 + 2]);
                        mma16816(d, ah[am], bl[nb][h2], bl[nb][h2 + 2]);
                        mma16816(d, al[am], bh[nb][h2], bh[nb][h2 + 2]);
                    }
        }
    }

    // epilogue: direct float2 stores
    const int er = lane >> 2, ec = (lane & 3) * 2;
#pragma unroll
    for (int am = 0; am < 2; ++am) {
        int row = m0 + wm * 32 + am * 16 + er;
#pragma unroll
        for (int na = 0; na < 8; ++na) {
            int col = n0 + wn * 64 + na * 8 + ec;
            float* d = acc[am][na];
            *reinterpret_cast<float2*>(C + (size_t)row * N + col)       = make_float2(d[0], d[1]);
            *reinterpret_cast<float2*>(C + (size_t)(row + 8) * N + col) = make_float2(d[2], d[3]);
        }
    }
}

// ============================================================================
// fp32 -> (hi,lo) bf16 split, elementwise (x4 vectorized)
// ============================================================================
__global__ __launch_bounds__(256) void split_bf16_k(
    const float* __restrict__ in, __nv_bfloat16* __restrict__ hi,
    __nv_bfloat16* __restrict__ lo, int n4)
{
    int i = blockIdx.x * 256 + threadIdx.x;
    if (i >= n4) return;
    float4 v = reinterpret_cast<const float4*>(in)[i];
    __nv_bfloat16 h0 = __float2bfloat16(v.x), h1 = __float2bfloat16(v.y);
    __nv_bfloat16 h2 = __float2bfloat16(v.z), h3 = __float2bfloat16(v.w);
    reinterpret_cast<__nv_bfloat162*>(hi)[2 * i]     = __halves2bfloat162(h0, h1);
    reinterpret_cast<__nv_bfloat162*>(hi)[2 * i + 1] = __halves2bfloat162(h2, h3);
    __nv_bfloat16 l0 = __float2bfloat16(v.x - __bfloat162float(h0));
    __nv_bfloat16 l1 = __float2bfloat16(v.y - __bfloat162float(h1));
    __nv_bfloat16 l2 = __float2bfloat16(v.z - __bfloat162float(h2));
    __nv_bfloat16 l3 = __float2bfloat16(v.w - __bfloat162float(h3));
    reinterpret_cast<__nv_bfloat162*>(lo)[2 * i]     = __halves2bfloat162(l0, l1);
    reinterpret_cast<__nv_bfloat162*>(lo)[2 * i + 1] = __halves2bfloat162(l2, l3);
}

// ============================================================================
// W[K,N] fp32 -> Wt hi/lo [N,K] bf16 (transpose + split)
// ============================================================================
__global__ __launch_bounds__(256) void tr_split_k(
    const float* __restrict__ W, __nv_bfloat16* __restrict__ hi,
    __nv_bfloat16* __restrict__ lo, int K, int N)
{
    __shared__ float t[32][33];
    const int k0 = blockIdx.y * 32, n0 = blockIdx.x * 32;
    const int tx = threadIdx.x & 31, ty = threadIdx.x >> 5;
#pragma unroll
    for (int i = 0; i < 4; ++i)
        t[ty + i * 8][tx] = W[(size_t)(k0 + ty + i * 8) * N + n0 + tx];
    __syncthreads();
#pragma unroll
    for (int i = 0; i < 4; ++i) {
        int n = n0 + ty + i * 8;
        float v = t[tx][ty + i * 8];
        __nv_bfloat16 h = __float2bfloat16(v);
        hi[(size_t)n * K + k0 + tx] = h;
        lo[(size_t)n * K + k0 + tx] = __float2bfloat16(v - __bfloat162float(h));
    }
}

// ============================================================================
// Depthwise causal conv (k=4) + bias + SiLU on x_ half of xz
// ============================================================================
__global__ __launch_bounds__(256) void conv_silu_k(
    const float* __restrict__ xz, const float* __restrict__ cw,
    const float* __restrict__ cb, float* __restrict__ xs)
{
    int idx = blockIdx.x * 256 + threadIdx.x;
    int d   = idx & (DINNER - 1);
    int row = idx >> 11;
    int l   = row & (LSEQ - 1);

    float acc = cb[d];
#pragma unroll
    for (int k = 0; k < 4; ++k) {
        int ls = l - 3 + k;
        float xv = (ls >= 0) ? xz[(size_t)(row - 3 + k) * XZW + d] : 0.f;
        acc = fmaf(cw[d * 4 + k], xv, acc);
    }
    xs[(size_t)row * DINNER + d] = acc / (1.f + __expf(-acc));
}

// ============================================================================
// bcd = xs @ W_x  (K=2048, N=33) -> B, C, delta
// ============================================================================
__global__ __launch_bounds__(256) void bcd_k(
    const float* __restrict__ xs, const float* __restrict__ Wx,
    float* __restrict__ gB, float* __restrict__ gC, float* __restrict__ gdelta)
{
    __shared__ float sX[32 * 33];
    __shared__ float sW[32 * 36];

    const int tid  = threadIdx.x;
    const int row0 = blockIdx.x * 32;
    const int row  = tid & 31;
    const int g    = tid >> 5;

    float acc0 = 0.f, acc1 = 0.f, acc2 = 0.f, acc3 = 0.f, accd = 0.f;

    for (int kc = 0; kc < DINNER; kc += 32) {
        for (int e = tid; e < 32 * 36; e += 256) {
            int k = e / 36, n = e - k * 36;
            sW[e] = (n < 33) ? Wx[(size_t)(kc + k) * 33 + n] : 0.f;
        }
        {
            int r = tid >> 3, c4 = tid & 7;
            float4 v = *(const float4*)(xs + (size_t)(row0 + r) * DINNER + kc + c4 * 4);
            int kk = c4 * 4;
            sX[(kk + 0) * 33 + r] = v.x;
            sX[(kk + 1) * 33 + r] = v.y;
            sX[(kk + 2) * 33 + r] = v.z;
            sX[(kk + 3) * 33 + r] = v.w;
        }
        __syncthreads();
#pragma unroll 8
        for (int k = 0; k < 32; ++k) {
            float  xv = sX[k * 33 + row];
            float4 wv = *(const float4*)(&sW[k * 36 + g * 4]);
            acc0 = fmaf(xv, wv.x, acc0);
            acc1 = fmaf(xv, wv.y, acc1);
            acc2 = fmaf(xv, wv.z, acc2);
            acc3 = fmaf(xv, wv.w, acc3);
            if (g == 0) accd = fmaf(xv, sW[k * 36 + 32], accd);
        }
        __syncthreads();
    }

    const int grow = row0 + row;
    float a[4] = {acc0, acc1, acc2, acc3};
#pragma unroll
    for (int j = 0; j < 4; ++j) {
        int nn = g * 4 + j;
        if (nn < 16) gB[(size_t)grow * 16 + nn]        = a[j];
        else         gC[(size_t)grow * 16 + (nn - 16)] = a[j];
    }
    if (g == 0) gdelta[grow] = accd;
}

// ============================================================================
// Selective scan + skip + gate + bf16 split.  Serial loop has NO shfl:
// each lane writes per-state partial h*C to padded smem; a parallel pass
// does the 16-way sum, skip, gate, and bf16 hi/lo split.
// Dynamic smem layout (floats):
//   [0)      sB   64*16
//   [1024)   sC   64*16
//   [2048)   sdt  64*16
//   [3072)   sx   64*16
//   [4096)   sz   64*16
//   [5120)   sp   64*272   (per-l row: 16 chains * stride 17)
//   [22528)  sDp  16
// ============================================================================
#define SCAN_SMEM_FLOATS (5120 + 64*272 + 16)

__global__ __launch_bounds__(256) void scan_k(
    const float* __restrict__ gdelta, const float* __restrict__ w_dt,
    const float* __restrict__ b_dt,
    const float* __restrict__ gxs,  const float* __restrict__ gxz,
    const float* __restrict__ gB,   const float* __restrict__ gC,
    const float* __restrict__ A_log, const float* __restrict__ Dp,
    __nv_bfloat16* __restrict__ yh, __nv_bfloat16* __restrict__ yl)
{
    extern __shared__ float sm[];
    float* sB  = sm;
    float* sC  = sm + 1024;
    float* sdt = sm + 2048;
    float* sx  = sm + 3072;
    float* sz  = sm + 4096;
    float* sp  = sm + 5120;
    float* sDp = sm + 22528;

    const int tid  = threadIdx.x;
    const int lane = tid & 31;
    const int w    = tid >> 5;
    const int cidx = 2 * w + (lane >> 4);
    const int n    = lane & 15;
    const int b    = blockIdx.x >> 7;
    const int d0   = (blockIdx.x & 127) * 16;
    const int d    = d0 + cidx;

    if (tid < 16) sDp[tid] = Dp[d0 + tid];

    const float A = -expf(A_log[d * DSTATE + n]);
    float h = 0.f;
    const int spb = cidx * 17 + n;   // this lane's partial slot within an l-row

    for (int t0 = 0; t0 < LSEQ; t0 += 64) {
        // ---- stage tiles (fused softplus for dt) ----
        {
            size_t base_bc = (size_t)(b * LSEQ + t0) * DSTATE;
            ((float4*)sB)[tid] = ((const float4*)(gB + base_bc))[tid];
            ((float4*)sC)[tid] = ((const float4*)(gC + base_bc))[tid];
#pragma unroll
            for (int i = 0; i < 4; ++i) {
                int e  = tid + i * 256;
                int l  = e >> 4, dd = e & 15;
                size_t grow = (size_t)(b * LSEQ + t0 + l);
                int dg = d0 + dd;
                float v = fmaf(gdelta[grow], w_dt[dg], b_dt[dg]);
                sdt[e] = (v > 30.f) ? v : log1pf(__expf(v));
                sx[e]  = gxs[grow * DINNER + dg];
                sz[e]  = gxz[grow * XZW + DINNER + dg];
            }
        }
        __syncthreads();

        // ---- 64 sequential steps: recurrence only, partials to smem ----
#pragma unroll 4
        for (int l = 0; l < 64; ++l) {
            float dt = sdt[l * 16 + cidx];
            float xv = sx [l * 16 + cidx];
            float a  = __expf(dt * A);
            h = fmaf(a, h, dt * xv * sB[l * 16 + n]);
            sp[l * 272 + spb] = h * sC[l * 16 + n];
        }
        __syncthreads();

        // ---- parallel 16-way sum + skip + gate + bf16 split + store ----
#pragma unroll
        for (int i = 0; i < 4; ++i) {
            int p  = tid + i * 256;          // (l, chain) pair
            int l  = p >> 4, ch = p & 15;
            const float* row = sp + l * 272 + ch * 17;
            float s = 0.f;
#pragma unroll
            for (int j = 0; j < 16; ++j) s += row[j];
            float xv = sx[l * 16 + ch];
            float y  = fmaf(xv, sDp[ch], s);
            float zv = sz[l * 16 + ch];
            float gv = y * (zv / (1.f + __expf(-zv)));
            size_t grow = (size_t)(b * LSEQ + t0 + l);
            __nv_bfloat16 hv = __float2bfloat16(gv);
            yh[grow * DINNER + d0 + ch] = hv;
            yl[grow * DINNER + d0 + ch] = __float2bfloat16(gv - __bfloat162float(hv));
        }
        __syncthreads();
    }
}

// ============================================================================
// launch
// ============================================================================
extern "C" void kernel_launch(void* const* d_in, const int* in_sizes, int n_in,
                              void* d_out, int out_size)
{
    const float* x     = (const float*)d_in[0];
    const float* W_in  = (const float*)d_in[1];
    const float* convw = (const float*)d_in[2];
    const float* convb = (const float*)d_in[3];
    const float* W_x   = (const float*)d_in[4];
    const float* w_dt  = (const float*)d_in[5];
    const float* b_dt  = (const float*)d_in[6];
    const float* A_log = (const float*)d_in[7];
    const float* Dp    = (const float*)d_in[8];
    const float* W_out = (const float*)d_in[9];
    float* out = (float*)d_out;

    float *p_xz, *p_xs, *p_B, *p_C, *p_delta;
    cudaGetSymbolAddress((void**)&p_xz,    g_xz);
    cudaGetSymbolAddress((void**)&p_xs,    g_xs);
    cudaGetSymbolAddress((void**)&p_B,     g_Bc);
    cudaGetSymbolAddress((void**)&p_C,     g_Cc);
    cudaGetSymbolAddress((void**)&p_delta, g_delta);

    __nv_bfloat16 *xa_h, *xa_l, *w1_h, *w1_l, *ya_h, *ya_l, *w2_h, *w2_l;
    cudaGetSymbolAddress((void**)&xa_h, g_xa_h);
    cudaGetSymbolAddress((void**)&xa_l, g_xa_l);
    cudaGetSymbolAddress((void**)&w1_h, g_w1_h);
    cudaGetSymbolAddress((void**)&w1_l, g_w1_l);
    cudaGetSymbolAddress((void**)&ya_h, g_ya_h);
    cudaGetSymbolAddress((void**)&ya_l, g_ya_l);
    cudaGetSymbolAddress((void**)&w2_h, g_w2_h);
    cudaGetSymbolAddress((void**)&w2_l, g_w2_l);

    constexpr int GSMEM = 3 * 65536;                       // 192 KB, 3 stages
    constexpr int SSMEM = SCAN_SMEM_FLOATS * 4;            // ~90 KB
    cudaFuncSetAttribute((const void*)gemm_mma,
                         cudaFuncAttributeMaxDynamicSharedMemorySize, GSMEM);
    cudaFuncSetAttribute((const void*)scan_k,
                         cudaFuncAttributeMaxDynamicSharedMemorySize, SSMEM);

    // prep: weight transpose+split, x split
    tr_split_k<<<dim3(XZW / 32, DMODEL / 32), 256>>>(W_in, w1_h, w1_l, DMODEL, XZW);
    tr_split_k<<<dim3(DMODEL / 32, DINNER / 32), 256>>>(W_out, w2_h, w2_l, DINNER, DMODEL);
    split_bf16_k<<<(NROWS * DMODEL / 4 + 255) / 256, 256>>>(x, xa_h, xa_l, NROWS * DMODEL / 4);

    // 1. xz = x @ W_in  (mma.sync bf16-split, 3-stage pipeline)
    gemm_mma<<<dim3(XZW / 128, NROWS / 128), 256, GSMEM>>>(
        xa_h, xa_l, w1_h, w1_l, p_xz, NROWS, XZW, DMODEL);

    // 2. xs = silu(conv(x_) + b)
    conv_silu_k<<<(NROWS * DINNER) / 256, 256>>>(p_xz, convw, convb, p_xs);

    // 3. B, C, delta
    bcd_k<<<NROWS / 32, 256>>>(p_xs, W_x, p_B, p_C, p_delta);

    // 4+5. selective scan (fused softplus, skip, gate, bf16 split)
    scan_k<<<BATCH * (DINNER / 16), 256, SSMEM>>>(
        p_delta, w_dt, b_dt, p_xs, p_xz, p_B, p_C, A_log, Dp, ya_h, ya_l);

    // 6. out = yz @ W_out  (mma.sync bf16-split)
    gemm_mma<<<dim3(DMODEL / 128, NROWS / 128), 256, GSMEM>>>(
        ya_h, ya_l, w2_h, w2_l, out, NROWS, DMODEL, DINNER);
}